// round 11
// baseline (speedup 1.0000x reference)
#include <cuda_runtime.h>
#include <cuda_bf16.h>
#include <math.h>
#include <stdint.h>

#define N_NODES 50000
#define N_EDGES 500000
#define F_IN 128
#define HID 160
#define F_OUTC 128
#define N_GRAPHS 50
#define OUT_DIM 10
#define PCHUNK 8

// ---------------- scratch (device globals) ----------------
__device__ float g_y [N_NODES * HID];
__device__ float g_h0[N_NODES * HID];
__device__ float g_h1[N_NODES * HID];
__device__ float g_dinv[N_NODES];
__device__ int   g_cnt[N_NODES];
__device__ int   g_off[N_NODES + 1];
__device__ int   g_cur[N_NODES];
__device__ int   g_adj[N_EDGES];
__device__ int   g_start[N_GRAPHS + 1];
__device__ float g_pp[N_GRAPHS * PCHUNK * F_OUTC];   // pool partials
__device__ float g_pooled[N_GRAPHS * F_OUTC];
__device__ int   g_is64_ei;
__device__ int   g_is64_batch;
// pre-split transposed weights: [layer][n(192)][k(192)] bf16 hi / lo (zero-padded)
__device__ __nv_bfloat16 g_wbh[4 * 192 * 192];
__device__ __nv_bfloat16 g_wbl[4 * 192 * 192];

__device__ __forceinline__ const float* sel_src(int s, const float* ext) {
    return (s == 0) ? ext : (s == 1 ? g_h0 : g_h1);
}
__device__ __forceinline__ float* sel_dst(int s) {
    return (s == 1) ? g_h0 : g_h1;
}
__device__ __forceinline__ int load_idx(const void* p, long long i, int is64, int lim) {
    int v = is64 ? (int)((const long long*)p)[i] : ((const int*)p)[i];
    v = v < 0 ? 0 : v;
    return v >= lim ? lim - 1 : v;
}
__device__ __forceinline__ void split_bf16(float a, __nv_bfloat16& h, __nv_bfloat16& l) {
    h = __float2bfloat16_rn(a);
    l = __float2bfloat16_rn(a - __bfloat162float(h));
}

// mma.sync m16n8k16 bf16 -> f32, D += A*B  (baseline PTX)
__device__ __forceinline__ void mma_bf16(float* d, const uint32_t* a, const uint32_t* b) {
    asm volatile(
        "mma.sync.aligned.m16n8k16.row.col.f32.bf16.bf16.f32 "
        "{%0,%1,%2,%3}, {%4,%5,%6,%7}, {%8,%9}, {%0,%1,%2,%3};\n"
        : "+f"(d[0]), "+f"(d[1]), "+f"(d[2]), "+f"(d[3])
        : "r"(a[0]), "r"(a[1]), "r"(a[2]), "r"(a[3]), "r"(b[0]), "r"(b[1]));
}

// ---------------- dtype detection ----------------
__global__ void k_detect(const unsigned* __restrict__ ei_raw,
                         const unsigned* __restrict__ batch_raw) {
    __shared__ int any_ei, any_b;
    if (threadIdx.x == 0) { any_ei = 0; any_b = 0; }
    __syncthreads();
    for (int i = threadIdx.x; i < 2048; i += blockDim.x) {
        if (ei_raw[2 * ((i * 487) % 499999) + 1] != 0) any_ei = 1;
        if (batch_raw[2 * ((i * 12) % 24999) + 1] != 0) any_b = 1;
    }
    __syncthreads();
    if (threadIdx.x == 0) { g_is64_ei = any_ei ? 0 : 1; g_is64_batch = any_b ? 0 : 1; }
}

// ---------------- CSR build ----------------
__global__ void k_init() {
    int i = blockIdx.x * blockDim.x + threadIdx.x;
    if (i < N_NODES) { g_cnt[i] = 0; g_cur[i] = 0; }
}
__global__ void k_count(const void* __restrict__ ei) {
    int e = blockIdx.x * blockDim.x + threadIdx.x;
    if (e < N_EDGES) {
        int d = load_idx(ei, (long long)N_EDGES + e, g_is64_ei, N_NODES);
        atomicAdd(&g_cnt[d], 1);
    }
}
// one-pass chunked scan; dinv computed here (fused)
__global__ void k_scan() {
    __shared__ int ts[1024];
    int tid = threadIdx.x;
    const int CH = 49;
    int base = tid * CH;
    int sum = 0;
    for (int i = 0; i < CH; i++) {
        int j = base + i;
        if (j < N_NODES) sum += g_cnt[j];
    }
    ts[tid] = sum;
    __syncthreads();
    for (int d = 1; d < 1024; d <<= 1) {
        int t = (tid >= d) ? ts[tid - d] : 0;
        __syncthreads();
        ts[tid] += t;
        __syncthreads();
    }
    int run = ts[tid] - sum;
    for (int i = 0; i < CH; i++) {
        int j = base + i;
        if (j < N_NODES) {
            int c = g_cnt[j];
            g_off[j] = run; run += c;
            g_dinv[j] = rsqrtf((float)c + 2.0f);
        }
    }
    if (tid == 1023) g_off[N_NODES] = run;
}
__global__ void k_fill(const void* __restrict__ ei) {
    int e = blockIdx.x * blockDim.x + threadIdx.x;
    if (e < N_EDGES) {
        int is64 = g_is64_ei;
        int s = load_idx(ei, e, is64, N_NODES);
        int d = load_idx(ei, (long long)N_EDGES + e, is64, N_NODES);
        int p = atomicAdd(&g_cur[d], 1);
        g_adj[g_off[d] + p] = s;
    }
}

// ---------------- weight transpose + pad + pre-split to bf16 hi/lo -------
__global__ void k_prepw(const float* __restrict__ W0, const float* __restrict__ W1,
                        const float* __restrict__ W2, const float* __restrict__ W3) {
    int l = blockIdx.y;
    const float* W = (l == 0) ? W0 : (l == 1) ? W1 : (l == 2) ? W2 : W3;
    int KA = (l == 0) ? F_IN : HID;
    int FOl = (l == 3) ? F_OUTC : HID;
    int idx = blockIdx.x * 256 + threadIdx.x;
    if (idx >= 192 * 192) return;
    int n = idx / 192, k = idx % 192;
    float v = (n < FOl && k < KA) ? W[k * FOl + n] : 0.f;
    __nv_bfloat16 h, lo;
    split_bf16(v, h, lo);
    g_wbh[l * 192 * 192 + idx] = h;
    g_wbl[l * 192 * 192 + idx] = lo;
}

// ---------------- mma.sync GEMM (R10 structure, unchanged) ----------------
#define ASTRIDE 144
#define BSTRIDE 144
#define OFF_AH 0
#define OFF_AL (128 * ASTRIDE)
#define OFF_BH (OFF_AL + 128 * ASTRIDE)
#define OFF_BL (OFF_BH + 64 * BSTRIDE)
#define SMEMSZ (OFF_BL + 64 * BSTRIDE)   // 55296

template <int K_ACT, int FO>
__global__ void __launch_bounds__(256) k_mma(const float* __restrict__ Aext,
                                             int asel, int layer) {
    extern __shared__ char smem[];
    const float* A = sel_src(asel, Aext);
    const __nv_bfloat16* WH = g_wbh + layer * 192 * 192;
    const __nv_bfloat16* WL = g_wbl + layer * 192 * 192;

    int tid = threadIdx.x;
    int wid = tid >> 5, lane = tid & 31;
    int row0 = blockIdx.x * 128;
    int col0 = blockIdx.y * 64;
    int lq = lane >> 2;
    int lr = lane & 3;

    constexpr int SLABS = (K_ACT + 63) / 64;

    float acc[8][4];
    #pragma unroll
    for (int nt = 0; nt < 8; nt++)
        #pragma unroll
        for (int j = 0; j < 4; j++) acc[nt][j] = 0.f;

    #pragma unroll 1
    for (int s = 0; s < SLABS; s++) {
        int kc = s * 64;
        int kmax = K_ACT - kc;
        int nks = (kmax >= 64) ? 4 : ((kmax + 15) >> 4);
        // ---- stage A: 128 rows x 64 k, fp32 -> bf16 hi/lo ----
        #pragma unroll
        for (int p = tid; p < 128 * 16; p += 256) {
            int r = p >> 4, c4 = p & 15;
            int gr = row0 + r;
            int k = kc + c4 * 4;
            float4 v = make_float4(0.f, 0.f, 0.f, 0.f);
            if (gr < N_NODES && k < K_ACT)
                v = *(const float4*)(A + (size_t)gr * K_ACT + k);
            __nv_bfloat16 hx, lx, hy, ly, hz, lz, hw, lw;
            split_bf16(v.x, hx, lx); split_bf16(v.y, hy, ly);
            split_bf16(v.z, hz, lz); split_bf16(v.w, hw, lw);
            char* ah = smem + OFF_AH + r * ASTRIDE + c4 * 8;
            char* al = smem + OFF_AL + r * ASTRIDE + c4 * 8;
            *(__nv_bfloat162*)(ah)     = __nv_bfloat162(hx, hy);
            *(__nv_bfloat162*)(ah + 4) = __nv_bfloat162(hz, hw);
            *(__nv_bfloat162*)(al)     = __nv_bfloat162(lx, ly);
            *(__nv_bfloat162*)(al + 4) = __nv_bfloat162(lz, lw);
        }
        // ---- stage B: pure copy from pre-split bf16 ----
        #pragma unroll
        for (int p = tid; p < 64 * 16; p += 256) {
            int r = p >> 4, c4 = p & 15;
            size_t go = (size_t)(col0 + r) * 192 + kc + c4 * 4;
            uint2 vh = *(const uint2*)(WH + go);
            uint2 vl = *(const uint2*)(WL + go);
            *(uint2*)(smem + OFF_BH + r * BSTRIDE + c4 * 8) = vh;
            *(uint2*)(smem + OFF_BL + r * BSTRIDE + c4 * 8) = vl;
        }
        __syncthreads();

        int rb = wid * 16;
        #pragma unroll
        for (int ks = 0; ks < 4; ks++) {
            if (ks >= nks) break;
            int k0 = ks * 16;
            uint32_t ah[4], al[4];
            {
                const char* baseh = smem + OFF_AH + (rb + lq) * ASTRIDE + (k0 + lr * 2) * 2;
                const char* basel = smem + OFF_AL + (rb + lq) * ASTRIDE + (k0 + lr * 2) * 2;
                ah[0] = *(const uint32_t*)(baseh);
                ah[1] = *(const uint32_t*)(baseh + 8 * ASTRIDE);
                ah[2] = *(const uint32_t*)(baseh + 16);
                ah[3] = *(const uint32_t*)(baseh + 8 * ASTRIDE + 16);
                al[0] = *(const uint32_t*)(basel);
                al[1] = *(const uint32_t*)(basel + 8 * ASTRIDE);
                al[2] = *(const uint32_t*)(basel + 16);
                al[3] = *(const uint32_t*)(basel + 8 * ASTRIDE + 16);
            }
            #pragma unroll
            for (int nt = 0; nt < 8; nt++) {
                uint32_t bh[2], bl[2];
                const char* bbh = smem + OFF_BH + (nt * 8 + lq) * BSTRIDE + (k0 + lr * 2) * 2;
                const char* bbl = smem + OFF_BL + (nt * 8 + lq) * BSTRIDE + (k0 + lr * 2) * 2;
                bh[0] = *(const uint32_t*)(bbh);
                bh[1] = *(const uint32_t*)(bbh + 16);
                bl[0] = *(const uint32_t*)(bbl);
                bl[1] = *(const uint32_t*)(bbl + 16);
                mma_bf16(acc[nt], ah, bh);
                mma_bf16(acc[nt], ah, bl);
                mma_bf16(acc[nt], al, bh);
            }
        }
        __syncthreads();
    }

    // ---- epilogue: scale by dinv, store ----
    int r0 = row0 + wid * 16 + lq;
    int r1 = r0 + 8;
    float dv0 = (r0 < N_NODES) ? g_dinv[r0] : 0.f;
    float dv1 = (r1 < N_NODES) ? g_dinv[r1] : 0.f;
    int cmax = FO - col0;
    #pragma unroll
    for (int nt = 0; nt < 8; nt++) {
        int cl = nt * 8 + lr * 2;
        if (cl >= cmax) continue;
        int c = col0 + cl;
        if (r0 < N_NODES)
            *(float2*)(g_y + (size_t)r0 * FO + c) =
                make_float2(dv0 * acc[nt][0], dv0 * acc[nt][1]);
        if (r1 < N_NODES)
            *(float2*)(g_y + (size_t)r1 * FO + c) =
                make_float2(dv1 * acc[nt][2], dv1 * acc[nt][3]);
    }
}

// ---------------- aggregation: warp per node (R5 form) ----------------
template <int FO>
__global__ void k_agg(const float* __restrict__ b, int osel) {
    float* out = sel_dst(osel);
    int warp = (blockIdx.x * blockDim.x + threadIdx.x) >> 5;
    int lane = threadIdx.x & 31;
    if (warp >= N_NODES) return;

    constexpr int J = FO / 32;
    float acc[J];
    const float* yi = g_y + (size_t)warp * FO;
    #pragma unroll
    for (int j = 0; j < J; j++) acc[j] = 2.f * yi[lane + 32 * j];

    int e0 = g_off[warp], e1 = g_off[warp + 1];
    for (int e = e0; e < e1; e++) {
        int s = g_adj[e];
        const float* ys = g_y + (size_t)s * FO;
        #pragma unroll
        for (int j = 0; j < J; j++) acc[j] += ys[lane + 32 * j];
    }

    float d = g_dinv[warp];
    #pragma unroll
    for (int j = 0; j < J; j++)
        out[(size_t)warp * FO + lane + 32 * j] = d * acc[j] + b[lane + 32 * j];
}

// ---------------- pooling / head ----------------
__global__ void k_bounds(const void* __restrict__ batch) {
    int i = blockIdx.x * blockDim.x + threadIdx.x;
    if (i >= N_NODES) return;
    int is64 = g_is64_batch;
    int b = load_idx(batch, i, is64, N_GRAPHS);
    if (i == 0) {
        for (int g = 0; g <= b; g++) g_start[g] = 0;
    } else {
        int pb = load_idx(batch, i - 1, is64, N_GRAPHS);
        if (pb != b) for (int g = pb + 1; g <= b; g++) g_start[g] = i;
    }
    if (i == N_NODES - 1) {
        for (int g = b + 1; g <= N_GRAPHS; g++) g_start[g] = N_NODES;
    }
}
// parallel pool: grid (N_GRAPHS, PCHUNK); partial sums, no atomics
__global__ void k_pool() {
    int g = blockIdx.x;
    int c = blockIdx.y;
    int f = threadIdx.x;   // 128
    int s = g_start[g], e = g_start[g + 1];
    int len = e - s;
    int n0 = s + (int)(((long long)len * c) / PCHUNK);
    int n1 = s + (int)(((long long)len * (c + 1)) / PCHUNK);
    float sum = 0.f;
    for (int n = n0; n < n1; n++) sum += g_h1[(size_t)n * F_OUTC + f];
    g_pp[(g * PCHUNK + c) * F_OUTC + f] = sum;
}
__global__ void k_pool2() {
    int g = blockIdx.x;
    int f = threadIdx.x;   // 128
    float sum = 0.f;
    #pragma unroll
    for (int c = 0; c < PCHUNK; c++)
        sum += g_pp[(g * PCHUNK + c) * F_OUTC + f];
    float cnt = (float)(g_start[g + 1] - g_start[g]);
    g_pooled[g * F_OUTC + f] = sum / fmaxf(cnt, 1.f);
}
__global__ void k_head(const float* __restrict__ fcw,
                       const float* __restrict__ fcb,
                       float* __restrict__ out) {
    int g = blockIdx.x;
    int lane = threadIdx.x;
    float logit = -INFINITY;
    if (lane < OUT_DIM) {
        float s = fcb[lane];
        #pragma unroll 8
        for (int k = 0; k < F_OUTC; k++)
            s += g_pooled[g * F_OUTC + k] * fcw[k * OUT_DIM + lane];
        logit = s;
    }
    float m = logit;
    #pragma unroll
    for (int o = 16; o > 0; o >>= 1)
        m = fmaxf(m, __shfl_xor_sync(0xffffffffu, m, o));
    float e = (lane < OUT_DIM) ? expf(logit - m) : 0.f;
    #pragma unroll
    for (int o = 16; o > 0; o >>= 1)
        e += __shfl_xor_sync(0xffffffffu, e, o);
    if (lane < OUT_DIM)
        out[g * OUT_DIM + lane] = logit - m - logf(e);
}

// ---------------- launch ----------------
extern "C" void kernel_launch(void* const* d_in, const int* in_sizes, int n_in,
                              void* d_out, int out_size) {
    const float* x     = (const float*)d_in[0];
    const void*  ei    = d_in[1];
    const void*  batch = d_in[2];
    const float* W0 = (const float*)d_in[3];  const float* b0 = (const float*)d_in[4];
    const float* W1 = (const float*)d_in[5];  const float* b1 = (const float*)d_in[6];
    const float* W2 = (const float*)d_in[7];  const float* b2 = (const float*)d_in[8];
    const float* W3 = (const float*)d_in[9];  const float* b3 = (const float*)d_in[10];
    const float* fcw = (const float*)d_in[11]; const float* fcb = (const float*)d_in[12];
    float* out = (float*)d_out;

    cudaFuncSetAttribute(k_mma<F_IN, HID>,
                         cudaFuncAttributeMaxDynamicSharedMemorySize, SMEMSZ);
    cudaFuncSetAttribute(k_mma<HID, HID>,
                         cudaFuncAttributeMaxDynamicSharedMemorySize, SMEMSZ);
    cudaFuncSetAttribute(k_mma<HID, F_OUTC>,
                         cudaFuncAttributeMaxDynamicSharedMemorySize, SMEMSZ);

    const int TB = 256;
    k_detect<<<1, 256>>>((const unsigned*)ei, (const unsigned*)batch);
    k_prepw<<<dim3((192 * 192 + 255) / 256, 4), 256>>>(W0, W1, W2, W3);
    k_init <<<(N_NODES + TB - 1) / TB, TB>>>();
    k_count<<<(N_EDGES + TB - 1) / TB, TB>>>(ei);
    k_scan <<<1, 1024>>>();
    k_fill <<<(N_EDGES + TB - 1) / TB, TB>>>(ei);

    const int RB = (N_NODES + 127) / 128;   // 391
    int aggBlocks = (N_NODES * 32 + TB - 1) / TB;

    dim3 gHid(RB, 3);
    dim3 gOut(RB, 2);

    k_mma<F_IN, HID><<<gHid, 256, SMEMSZ>>>(x, 0, 0);
    k_agg<HID><<<aggBlocks, TB>>>(b0, 1);
    k_mma<HID, HID><<<gHid, 256, SMEMSZ>>>(nullptr, 1, 1);
    k_agg<HID><<<aggBlocks, TB>>>(b1, 2);
    k_mma<HID, HID><<<gHid, 256, SMEMSZ>>>(nullptr, 2, 2);
    k_agg<HID><<<aggBlocks, TB>>>(b2, 1);
    k_mma<HID, F_OUTC><<<gOut, 256, SMEMSZ>>>(nullptr, 1, 3);
    k_agg<F_OUTC><<<aggBlocks, TB>>>(b3, 2);

    k_bounds<<<(N_NODES + TB - 1) / TB, TB>>>(batch);
    k_pool<<<dim3(N_GRAPHS, PCHUNK), F_OUTC>>>();
    k_pool2<<<N_GRAPHS, F_OUTC>>>();
    k_head<<<N_GRAPHS, 32>>>(fcw, fcb, out);
}

// round 12
// speedup vs baseline: 1.0384x; 1.0384x over previous
#include <cuda_runtime.h>
#include <cuda_bf16.h>
#include <math.h>
#include <stdint.h>

#define N_NODES 50000
#define N_EDGES 500000
#define F_IN 128
#define HID 160
#define F_OUTC 128
#define N_GRAPHS 50
#define OUT_DIM 10

// ---------------- scratch (device globals) ----------------
__device__ float g_y [N_NODES * HID];
__device__ float g_h0[N_NODES * HID];
__device__ float g_h1[N_NODES * HID];
__device__ float g_dinv[N_NODES];
__device__ int   g_cnt[N_NODES];
__device__ int   g_off[N_NODES + 1];
__device__ int   g_cur[N_NODES];
__device__ int   g_adj[N_EDGES];
__device__ int   g_start[N_GRAPHS + 1];
__device__ float g_pooled[N_GRAPHS * F_OUTC];
__device__ int   g_is64_ei;
__device__ int   g_is64_batch;
// pre-split transposed weights: [layer][n(192)][k(192)] bf16 hi / lo (zero-padded)
__device__ __nv_bfloat16 g_wbh[4 * 192 * 192];
__device__ __nv_bfloat16 g_wbl[4 * 192 * 192];

__device__ __forceinline__ const float* sel_src(int s, const float* ext) {
    return (s == 0) ? ext : (s == 1 ? g_h0 : g_h1);
}
__device__ __forceinline__ float* sel_dst(int s) {
    return (s == 1) ? g_h0 : g_h1;
}
__device__ __forceinline__ int load_idx(const void* p, long long i, int is64, int lim) {
    int v = is64 ? (int)((const long long*)p)[i] : ((const int*)p)[i];
    v = v < 0 ? 0 : v;
    return v >= lim ? lim - 1 : v;
}
__device__ __forceinline__ void split_bf16(float a, __nv_bfloat16& h, __nv_bfloat16& l) {
    h = __float2bfloat16_rn(a);
    l = __float2bfloat16_rn(a - __bfloat162float(h));
}

// mma.sync m16n8k16 bf16 -> f32, D += A*B  (baseline PTX)
__device__ __forceinline__ void mma_bf16(float* d, const uint32_t* a, const uint32_t* b) {
    asm volatile(
        "mma.sync.aligned.m16n8k16.row.col.f32.bf16.bf16.f32 "
        "{%0,%1,%2,%3}, {%4,%5,%6,%7}, {%8,%9}, {%0,%1,%2,%3};\n"
        : "+f"(d[0]), "+f"(d[1]), "+f"(d[2]), "+f"(d[3])
        : "r"(a[0]), "r"(a[1]), "r"(a[2]), "r"(a[3]), "r"(b[0]), "r"(b[1]));
}

// ---------------- dtype detection ----------------
__global__ void k_detect(const unsigned* __restrict__ ei_raw,
                         const unsigned* __restrict__ batch_raw) {
    __shared__ int any_ei, any_b;
    if (threadIdx.x == 0) { any_ei = 0; any_b = 0; }
    __syncthreads();
    for (int i = threadIdx.x; i < 2048; i += blockDim.x) {
        if (ei_raw[2 * ((i * 487) % 499999) + 1] != 0) any_ei = 1;
        if (batch_raw[2 * ((i * 12) % 24999) + 1] != 0) any_b = 1;
    }
    __syncthreads();
    if (threadIdx.x == 0) { g_is64_ei = any_ei ? 0 : 1; g_is64_batch = any_b ? 0 : 1; }
}

// ---------------- CSR build ----------------
__global__ void k_init() {
    int i = blockIdx.x * blockDim.x + threadIdx.x;
    if (i < N_NODES) { g_cnt[i] = 0; g_cur[i] = 0; }
}
__global__ void k_count(const void* __restrict__ ei) {
    int e = blockIdx.x * blockDim.x + threadIdx.x;
    if (e < N_EDGES) {
        int d = load_idx(ei, (long long)N_EDGES + e, g_is64_ei, N_NODES);
        atomicAdd(&g_cnt[d], 1);
    }
}
__global__ void k_dinv() {
    int i = blockIdx.x * blockDim.x + threadIdx.x;
    if (i < N_NODES) g_dinv[i] = rsqrtf((float)g_cnt[i] + 2.0f);
}
// one-pass chunked scan
__global__ void k_scan() {
    __shared__ int ts[1024];
    int tid = threadIdx.x;
    const int CH = 49;
    int base = tid * CH;
    int sum = 0;
    for (int i = 0; i < CH; i++) {
        int j = base + i;
        if (j < N_NODES) sum += g_cnt[j];
    }
    ts[tid] = sum;
    __syncthreads();
    for (int d = 1; d < 1024; d <<= 1) {
        int t = (tid >= d) ? ts[tid - d] : 0;
        __syncthreads();
        ts[tid] += t;
        __syncthreads();
    }
    int run = ts[tid] - sum;
    for (int i = 0; i < CH; i++) {
        int j = base + i;
        if (j < N_NODES) { g_off[j] = run; run += g_cnt[j]; }
    }
    if (tid == 1023) g_off[N_NODES] = run;
}
__global__ void k_fill(const void* __restrict__ ei) {
    int e = blockIdx.x * blockDim.x + threadIdx.x;
    if (e < N_EDGES) {
        int is64 = g_is64_ei;
        int s = load_idx(ei, e, is64, N_NODES);
        int d = load_idx(ei, (long long)N_EDGES + e, is64, N_NODES);
        int p = atomicAdd(&g_cur[d], 1);
        g_adj[g_off[d] + p] = s;
    }
}

// ---------------- weight transpose + pad + pre-split to bf16 hi/lo -------
__global__ void k_prepw(const float* __restrict__ W0, const float* __restrict__ W1,
                        const float* __restrict__ W2, const float* __restrict__ W3) {
    int l = blockIdx.y;
    const float* W = (l == 0) ? W0 : (l == 1) ? W1 : (l == 2) ? W2 : W3;
    int KA = (l == 0) ? F_IN : HID;
    int FOl = (l == 3) ? F_OUTC : HID;
    int idx = blockIdx.x * 256 + threadIdx.x;
    if (idx >= 192 * 192) return;
    int n = idx / 192, k = idx % 192;
    float v = (n < FOl && k < KA) ? W[k * FOl + n] : 0.f;
    __nv_bfloat16 h, lo;
    split_bf16(v, h, lo);
    g_wbh[l * 192 * 192 + idx] = h;
    g_wbl[l * 192 * 192 + idx] = lo;
}

// ---------------- mma.sync GEMM (R10 structure; 3 blocks/SM forced) ------
#define ASTRIDE 144
#define BSTRIDE 144
#define OFF_AH 0
#define OFF_AL (128 * ASTRIDE)
#define OFF_BH (OFF_AL + 128 * ASTRIDE)
#define OFF_BL (OFF_BH + 64 * BSTRIDE)
#define SMEMSZ (OFF_BL + 64 * BSTRIDE)   // 55296

template <int K_ACT, int FO>
__global__ void __launch_bounds__(256, 3) k_mma(const float* __restrict__ Aext,
                                                int asel, int layer) {
    extern __shared__ char smem[];
    const float* A = sel_src(asel, Aext);
    const __nv_bfloat16* WH = g_wbh + layer * 192 * 192;
    const __nv_bfloat16* WL = g_wbl + layer * 192 * 192;

    int tid = threadIdx.x;
    int wid = tid >> 5, lane = tid & 31;
    int row0 = blockIdx.x * 128;
    int col0 = blockIdx.y * 64;
    int lq = lane >> 2;
    int lr = lane & 3;

    constexpr int SLABS = (K_ACT + 63) / 64;

    float acc[8][4];
    #pragma unroll
    for (int nt = 0; nt < 8; nt++)
        #pragma unroll
        for (int j = 0; j < 4; j++) acc[nt][j] = 0.f;

    #pragma unroll 1
    for (int s = 0; s < SLABS; s++) {
        int kc = s * 64;
        int kmax = K_ACT - kc;
        int nks = (kmax >= 64) ? 4 : ((kmax + 15) >> 4);
        // ---- stage A: 128 rows x 64 k, fp32 -> bf16 hi/lo ----
        #pragma unroll
        for (int p = tid; p < 128 * 16; p += 256) {
            int r = p >> 4, c4 = p & 15;
            int gr = row0 + r;
            int k = kc + c4 * 4;
            float4 v = make_float4(0.f, 0.f, 0.f, 0.f);
            if (gr < N_NODES && k < K_ACT)
                v = *(const float4*)(A + (size_t)gr * K_ACT + k);
            __nv_bfloat16 hx, lx, hy, ly, hz, lz, hw, lw;
            split_bf16(v.x, hx, lx); split_bf16(v.y, hy, ly);
            split_bf16(v.z, hz, lz); split_bf16(v.w, hw, lw);
            char* ah = smem + OFF_AH + r * ASTRIDE + c4 * 8;
            char* al = smem + OFF_AL + r * ASTRIDE + c4 * 8;
            *(__nv_bfloat162*)(ah)     = __nv_bfloat162(hx, hy);
            *(__nv_bfloat162*)(ah + 4) = __nv_bfloat162(hz, hw);
            *(__nv_bfloat162*)(al)     = __nv_bfloat162(lx, ly);
            *(__nv_bfloat162*)(al + 4) = __nv_bfloat162(lz, lw);
        }
        // ---- stage B: pure copy from pre-split bf16 ----
        #pragma unroll
        for (int p = tid; p < 64 * 16; p += 256) {
            int r = p >> 4, c4 = p & 15;
            size_t go = (size_t)(col0 + r) * 192 + kc + c4 * 4;
            uint2 vh = *(const uint2*)(WH + go);
            uint2 vl = *(const uint2*)(WL + go);
            *(uint2*)(smem + OFF_BH + r * BSTRIDE + c4 * 8) = vh;
            *(uint2*)(smem + OFF_BL + r * BSTRIDE + c4 * 8) = vl;
        }
        __syncthreads();

        int rb = wid * 16;
        #pragma unroll
        for (int ks = 0; ks < 4; ks++) {
            if (ks >= nks) break;
            int k0 = ks * 16;
            uint32_t ah[4], al[4];
            {
                const char* baseh = smem + OFF_AH + (rb + lq) * ASTRIDE + (k0 + lr * 2) * 2;
                const char* basel = smem + OFF_AL + (rb + lq) * ASTRIDE + (k0 + lr * 2) * 2;
                ah[0] = *(const uint32_t*)(baseh);
                ah[1] = *(const uint32_t*)(baseh + 8 * ASTRIDE);
                ah[2] = *(const uint32_t*)(baseh + 16);
                ah[3] = *(const uint32_t*)(baseh + 8 * ASTRIDE + 16);
                al[0] = *(const uint32_t*)(basel);
                al[1] = *(const uint32_t*)(basel + 8 * ASTRIDE);
                al[2] = *(const uint32_t*)(basel + 16);
                al[3] = *(const uint32_t*)(basel + 8 * ASTRIDE + 16);
            }
            #pragma unroll
            for (int nt = 0; nt < 8; nt++) {
                uint32_t bh[2], bl[2];
                const char* bbh = smem + OFF_BH + (nt * 8 + lq) * BSTRIDE + (k0 + lr * 2) * 2;
                const char* bbl = smem + OFF_BL + (nt * 8 + lq) * BSTRIDE + (k0 + lr * 2) * 2;
                bh[0] = *(const uint32_t*)(bbh);
                bh[1] = *(const uint32_t*)(bbh + 16);
                bl[0] = *(const uint32_t*)(bbl);
                bl[1] = *(const uint32_t*)(bbl + 16);
                mma_bf16(acc[nt], ah, bh);
                mma_bf16(acc[nt], ah, bl);
                mma_bf16(acc[nt], al, bh);
            }
        }
        __syncthreads();
    }

    // ---- epilogue: scale by dinv, store ----
    int r0 = row0 + wid * 16 + lq;
    int r1 = r0 + 8;
    float dv0 = (r0 < N_NODES) ? g_dinv[r0] : 0.f;
    float dv1 = (r1 < N_NODES) ? g_dinv[r1] : 0.f;
    int cmax = FO - col0;
    #pragma unroll
    for (int nt = 0; nt < 8; nt++) {
        int cl = nt * 8 + lr * 2;
        if (cl >= cmax) continue;
        int c = col0 + cl;
        if (r0 < N_NODES)
            *(float2*)(g_y + (size_t)r0 * FO + c) =
                make_float2(dv0 * acc[nt][0], dv0 * acc[nt][1]);
        if (r1 < N_NODES)
            *(float2*)(g_y + (size_t)r1 * FO + c) =
                make_float2(dv1 * acc[nt][2], dv1 * acc[nt][3]);
    }
}

// ---------------- aggregation: warp per node (R5 form) ----------------
template <int FO>
__global__ void k_agg(const float* __restrict__ b, int osel) {
    float* out = sel_dst(osel);
    int warp = (blockIdx.x * blockDim.x + threadIdx.x) >> 5;
    int lane = threadIdx.x & 31;
    if (warp >= N_NODES) return;

    constexpr int J = FO / 32;
    float acc[J];
    const float* yi = g_y + (size_t)warp * FO;
    #pragma unroll
    for (int j = 0; j < J; j++) acc[j] = 2.f * yi[lane + 32 * j];

    int e0 = g_off[warp], e1 = g_off[warp + 1];
    for (int e = e0; e < e1; e++) {
        int s = g_adj[e];
        const float* ys = g_y + (size_t)s * FO;
        #pragma unroll
        for (int j = 0; j < J; j++) acc[j] += ys[lane + 32 * j];
    }

    float d = g_dinv[warp];
    #pragma unroll
    for (int j = 0; j < J; j++)
        out[(size_t)warp * FO + lane + 32 * j] = d * acc[j] + b[lane + 32 * j];
}

// ---------------- pooling / head ----------------
__global__ void k_bounds(const void* __restrict__ batch) {
    int i = blockIdx.x * blockDim.x + threadIdx.x;
    if (i >= N_NODES) return;
    int is64 = g_is64_batch;
    int b = load_idx(batch, i, is64, N_GRAPHS);
    if (i == 0) {
        for (int g = 0; g <= b; g++) g_start[g] = 0;
    } else {
        int pb = load_idx(batch, i - 1, is64, N_GRAPHS);
        if (pb != b) for (int g = pb + 1; g <= b; g++) g_start[g] = i;
    }
    if (i == N_NODES - 1) {
        for (int g = b + 1; g <= N_GRAPHS; g++) g_start[g] = N_NODES;
    }
}
__global__ void k_pool() {
    int g = blockIdx.x;
    int f = threadIdx.x;
    int s = g_start[g], e = g_start[g + 1];
    float sum = 0.f;
    for (int n = s; n < e; n++) sum += g_h1[(size_t)n * F_OUTC + f];
    float c = (float)(e - s);
    g_pooled[g * F_OUTC + f] = sum / fmaxf(c, 1.f);
}
__global__ void k_head(const float* __restrict__ fcw,
                       const float* __restrict__ fcb,
                       float* __restrict__ out) {
    int g = blockIdx.x;
    int lane = threadIdx.x;
    float logit = -INFINITY;
    if (lane < OUT_DIM) {
        float s = fcb[lane];
        #pragma unroll 8
        for (int k = 0; k < F_OUTC; k++)
            s += g_pooled[g * F_OUTC + k] * fcw[k * OUT_DIM + lane];
        logit = s;
    }
    float m = logit;
    #pragma unroll
    for (int o = 16; o > 0; o >>= 1)
        m = fmaxf(m, __shfl_xor_sync(0xffffffffu, m, o));
    float e = (lane < OUT_DIM) ? expf(logit - m) : 0.f;
    #pragma unroll
    for (int o = 16; o > 0; o >>= 1)
        e += __shfl_xor_sync(0xffffffffu, e, o);
    if (lane < OUT_DIM)
        out[g * OUT_DIM + lane] = logit - m - logf(e);
}

// ---------------- launch ----------------
extern "C" void kernel_launch(void* const* d_in, const int* in_sizes, int n_in,
                              void* d_out, int out_size) {
    const float* x     = (const float*)d_in[0];
    const void*  ei    = d_in[1];
    const void*  batch = d_in[2];
    const float* W0 = (const float*)d_in[3];  const float* b0 = (const float*)d_in[4];
    const float* W1 = (const float*)d_in[5];  const float* b1 = (const float*)d_in[6];
    const float* W2 = (const float*)d_in[7];  const float* b2 = (const float*)d_in[8];
    const float* W3 = (const float*)d_in[9];  const float* b3 = (const float*)d_in[10];
    const float* fcw = (const float*)d_in[11]; const float* fcb = (const float*)d_in[12];
    float* out = (float*)d_out;

    cudaFuncSetAttribute(k_mma<F_IN, HID>,
                         cudaFuncAttributeMaxDynamicSharedMemorySize, SMEMSZ);
    cudaFuncSetAttribute(k_mma<HID, HID>,
                         cudaFuncAttributeMaxDynamicSharedMemorySize, SMEMSZ);
    cudaFuncSetAttribute(k_mma<HID, F_OUTC>,
                         cudaFuncAttributeMaxDynamicSharedMemorySize, SMEMSZ);

    const int TB = 256;
    k_detect<<<1, 256>>>((const unsigned*)ei, (const unsigned*)batch);
    k_prepw<<<dim3((192 * 192 + 255) / 256, 4), 256>>>(W0, W1, W2, W3);
    k_init <<<(N_NODES + TB - 1) / TB, TB>>>();
    k_count<<<(N_EDGES + TB - 1) / TB, TB>>>(ei);
    k_dinv <<<(N_NODES + TB - 1) / TB, TB>>>();
    k_scan <<<1, 1024>>>();
    k_fill <<<(N_EDGES + TB - 1) / TB, TB>>>(ei);

    const int RB = (N_NODES + 127) / 128;   // 391
    int aggBlocks = (N_NODES * 32 + TB - 1) / TB;

    dim3 gHid(RB, 3);
    dim3 gOut(RB, 2);

    k_mma<F_IN, HID><<<gHid, 256, SMEMSZ>>>(x, 0, 0);
    k_agg<HID><<<aggBlocks, TB>>>(b0, 1);
    k_mma<HID, HID><<<gHid, 256, SMEMSZ>>>(nullptr, 1, 1);
    k_agg<HID><<<aggBlocks, TB>>>(b1, 2);
    k_mma<HID, HID><<<gHid, 256, SMEMSZ>>>(nullptr, 2, 2);
    k_agg<HID><<<aggBlocks, TB>>>(b2, 1);
    k_mma<HID, F_OUTC><<<gOut, 256, SMEMSZ>>>(nullptr, 1, 3);
    k_agg<F_OUTC><<<aggBlocks, TB>>>(b3, 2);

    k_bounds<<<(N_NODES + TB - 1) / TB, TB>>>(batch);
    k_pool<<<N_GRAPHS, F_OUTC>>>();
    k_head<<<N_GRAPHS, 32>>>(fcw, fcb, out);
}